// round 13
// baseline (speedup 1.0000x reference)
#include <cuda_runtime.h>
#include <cstdint>
#include <cstddef>

#define BATCH   16384
#define WIDTH   128
#define NNODES  12
#define NEDGES  66
#define NCHUNKS 132                        // sum over v of 2v (BK=64 chunks)

#define BM 128
#define THREADS 544                        // 16 consumer warps + 1 producer warp
#define TILE_BYTES (128 * 64)              // 128 rows x 64 int8 = 8 KB
#define STAGE_BYTES (4 * TILE_BYTES)       // A1, A0, W1, W0 = 32 KB
#define NSTAGE 5
#define SUM_OFF 1024
#define SUM_BYTES (8 * 512 * 16)           // 64 KB: float4 sumv[8][512]
#define STAGE0_OFF (SUM_OFF + SUM_BYTES)
#define SMEM_TOTAL (STAGE0_OFF + NSTAGE * STAGE_BYTES)   // 230400 B

#define MB_FULL(s)  ((s) * 8)              // 0..39
#define MB_EMPTY(s) (40 + (s) * 8)         // 40..79
#define SA_OFF  96                          // float sA_sm[12]
#define RED_OFF 160                         // float red[17]

#define OFF_A1 0
#define OFF_A0 TILE_BYTES
#define OFF_W1 (2 * TILE_BYTES)
#define OFF_W0 (3 * TILE_BYTES)

// ---------------- device scratch ----------------
__device__ int8_t g_A1[11u * BATCH * WIDTH];
__device__ int8_t g_A0[11u * BATCH * WIDTH];
__device__ int8_t g_W1[(size_t)NEDGES * WIDTH * WIDTH];   // [e][n][k] transposed
__device__ int8_t g_W0[(size_t)NEDGES * WIDTH * WIDTH];
__device__ float  g_sWfold[NEDGES];  // sW / 16256^2

// ---------------- PTX helpers ----------------
__device__ __forceinline__ uint32_t smem_u32(const void* p) {
    uint32_t a;
    asm("{ .reg .u64 t; cvta.to.shared.u64 t, %1; cvt.u32.u64 %0, t; }" : "=r"(a) : "l"(p));
    return a;
}
__device__ __forceinline__ void mbar_init(uint32_t a, uint32_t cnt) {
    asm volatile("mbarrier.init.shared.b64 [%0], %1;" :: "r"(a), "r"(cnt) : "memory");
}
__device__ __forceinline__ void mbar_arrive(uint32_t a) {
    asm volatile("mbarrier.arrive.shared.b64 _, [%0];" :: "r"(a) : "memory");
}
__device__ __forceinline__ void mbar_wait(uint32_t a, uint32_t parity) {
    asm volatile(
        "{\n\t.reg .pred P;\n\t"
        "WL%=:\n\t"
        "mbarrier.try_wait.parity.acquire.cta.shared::cta.b64 P, [%0], %1, 0x989680;\n\t"
        "@!P bra WL%=;\n\t}"
        :: "r"(a), "r"(parity) : "memory");
}
__device__ __forceinline__ void cp_async16(uint32_t dst, const void* src) {
    asm volatile("cp.async.cg.shared.global [%0], [%1], 16;" :: "r"(dst), "l"(src) : "memory");
}
__device__ __forceinline__ void cp_async_arrive_noinc(uint32_t mbar) {
    asm volatile("cp.async.mbarrier.arrive.noinc.shared.b64 [%0];" :: "r"(mbar) : "memory");
}
__device__ __forceinline__ void ldsm4(uint32_t& r0, uint32_t& r1, uint32_t& r2, uint32_t& r3,
                                      uint32_t addr) {
    asm volatile("ldmatrix.sync.aligned.m8n8.x4.shared.b16 {%0,%1,%2,%3}, [%4];"
                 : "=r"(r0), "=r"(r1), "=r"(r2), "=r"(r3) : "r"(addr));
}
__device__ __forceinline__ void mma_s8(int& d0, int& d1, int& d2, int& d3,
                                       uint32_t a0, uint32_t a1, uint32_t a2, uint32_t a3,
                                       uint32_t b0, uint32_t b1) {
    asm volatile(
        "mma.sync.aligned.m16n8k32.row.col.s32.s8.s8.s32 "
        "{%0,%1,%2,%3}, {%4,%5,%6,%7}, {%8,%9}, {%0,%1,%2,%3};"
        : "+r"(d0), "+r"(d1), "+r"(d2), "+r"(d3)
        : "r"(a0), "r"(a1), "r"(a2), "r"(a3), "r"(b0), "r"(b1));
}
__device__ __forceinline__ void bar512() {
    asm volatile("bar.sync 1, 512;" ::: "memory");
}

// swizzled tile address: 128 rows x 64B, 2 rows per 128B line, XOR by line index
__device__ __forceinline__ uint32_t tile_addr(int m, int cc) {
    return (uint32_t)((m >> 1) * 128 + (((((m & 1) << 2) | cc) ^ ((m >> 1) & 7)) << 4));
}

__device__ __forceinline__ void quant2(float h, float inv, int& hi, int& lo) {
    float qf = rintf(h * inv);                 // |qf| <= 16256
    float f1 = rintf(qf * 0.0078125f);         // /128
    hi = (int)f1;
    lo = (int)(qf - 128.0f * f1);              // in [-64, 64]
}

// ---------------- W preprocessing: max + transpose + quantize (one kernel) ----------------
__global__ void w_prep_kernel(const float* __restrict__ W) {
    __shared__ float t[32][33];
    __shared__ float red[8];
    __shared__ float qs_sm;
    const int e = blockIdx.x;
    const int tx = threadIdx.x, ty = threadIdx.y;      // 32 x 8
    const int tid = ty * 32 + tx;
    const float* Wb = W + (size_t)e * WIDTH * WIDTH;

    float mx = 0.f;
    for (int i = tid; i < WIDTH * WIDTH; i += 256) mx = fmaxf(mx, fabsf(Wb[i]));
    for (int o = 16; o; o >>= 1) mx = fmaxf(mx, __shfl_xor_sync(0xffffffffu, mx, o));
    if (tx == 0) red[ty] = mx;
    __syncthreads();
    if (tid == 0) {
        mx = red[0];
#pragma unroll
        for (int i = 1; i < 8; i++) mx = fmaxf(mx, red[i]);
        mx = fmaxf(mx, 1e-30f);
        qs_sm = 16256.0f / mx;
        g_sWfold[e] = mx / (16256.0f * 16256.0f);
    }
    __syncthreads();
    const float qs = qs_sm;
    int8_t* H1 = g_W1 + (size_t)e * WIDTH * WIDTH;
    int8_t* H0 = g_W0 + (size_t)e * WIDTH * WIDTH;

    for (int ti = 0; ti < 16; ti++) {
        const int kt = (ti & 3) * 32;
        const int nt = (ti >> 2) * 32;
#pragma unroll
        for (int r = 0; r < 32; r += 8)
            t[ty + r][tx] = Wb[(kt + ty + r) * WIDTH + nt + tx];
        __syncthreads();
#pragma unroll
        for (int r = 0; r < 32; r += 8) {
            const int n = nt + ty + r;
            float v = t[tx][ty + r];
            int hi, lo;
            quant2(v, qs, hi, lo);
            H1[n * WIDTH + kt + tx] = (int8_t)hi;
            H0[n * WIDTH + kt + tx] = (int8_t)lo;
        }
        __syncthreads();
    }
}

// chunk cursor
struct Cursor {
    int v, e, kc, w;
    __device__ __forceinline__ void init() { v = 1; e = 0; kc = 0; w = 0; }
    __device__ __forceinline__ void advance() {
        if (kc == 0) { kc = 1; return; }
        kc = 0; e++; w++;
        if (e == v) { e = 0; v++; w = v * (v - 1) / 2; }
    }
};

// ---------------- fused kernel ----------------
__global__ void __launch_bounds__(THREADS, 1) node_fused_kernel(
    const float* __restrict__ x,
    const float* __restrict__ bias,
    float* __restrict__ out)
{
    extern __shared__ __align__(1024) char smem[];
    const uint32_t sbase = smem_u32(smem);
    float*  sA_sm = (float*)(smem + SA_OFF);
    float*  red   = (float*)(smem + RED_OFF);
    float4* sumv  = (float4*)(smem + SUM_OFF);

    const int tid  = threadIdx.x;
    const int lane = tid & 31;
    const int wid  = tid >> 5;
    const int row0 = blockIdx.x * BM;

    if (tid == 0) {
#pragma unroll
        for (int s = 0; s < NSTAGE; s++) {
            mbar_init(sbase + MB_FULL(s), 32);
            mbar_init(sbase + MB_EMPTY(s), 16);
        }
    }

    // ---- x quantization for this CTA's 128 rows ----
    {
        const float4* xs = (const float4*)(x + (size_t)row0 * WIDTH);
        float mx = 0.f;
        for (int i = tid; i < 4096; i += THREADS) {
            float4 v = xs[i];
            mx = fmaxf(mx, fmaxf(fmaxf(fabsf(v.x), fabsf(v.y)), fmaxf(fabsf(v.z), fabsf(v.w))));
        }
        for (int o = 16; o; o >>= 1) mx = fmaxf(mx, __shfl_xor_sync(0xffffffffu, mx, o));
        if (lane == 0) red[wid] = mx;
        __syncthreads();
        mx = red[0];
#pragma unroll
        for (int i = 1; i < 17; i++) mx = fmaxf(mx, red[i]);
        const float sA = fmaxf(mx, 1e-30f);
        if (tid == 0) sA_sm[0] = sA;
        const float inv = 16256.0f / sA;
        for (int i = tid; i < 4096; i += THREADS) {
            float4 v = xs[i];
            int h0, l0, h1, l1, h2, l2, h3, l3;
            quant2(v.x, inv, h0, l0); quant2(v.y, inv, h1, l1);
            quant2(v.z, inv, h2, l2); quant2(v.w, inv, h3, l3);
            *(char4*)(g_A1 + (size_t)row0 * WIDTH + (size_t)i * 4) =
                make_char4((char)h0, (char)h1, (char)h2, (char)h3);
            *(char4*)(g_A0 + (size_t)row0 * WIDTH + (size_t)i * 4) =
                make_char4((char)l0, (char)l1, (char)l2, (char)l3);
        }
    }
    __syncthreads();   // x data + barriers + sA_sm[0] visible

    if (wid == 16) {
        // ================= PRODUCER WARP =================
        Cursor pf; pf.init();
        int empty_par[NSTAGE] = {0, 0, 0, 0, 0};
        for (int g = 0; g < NCHUNKS; g++) {
            const int s = g % NSTAGE;
            if (g >= NSTAGE) {
                mbar_wait(sbase + MB_EMPTY(s), empty_par[s]);
                empty_par[s] ^= 1;
            }
            // RAW hazard (v=1): chunk 4 reads node-1 output written at chunk 1;
            // the g-NSTAGE back-wait doesn't cover it. Wait chunk 1 fully done.
            if (g == 4) mbar_wait(sbase + MB_EMPTY(1), 0);
            const uint32_t stb = sbase + STAGE0_OFF + s * STAGE_BYTES;
            const size_t abase = (size_t)pf.e * (BATCH * WIDTH) + (size_t)row0 * WIDTH + pf.kc * 64;
            const size_t wbase = (size_t)pf.w * (WIDTH * WIDTH) + pf.kc * 64;
#pragma unroll
            for (int j = 0; j < 16; j++) {
                const int idx = j * 32 + lane;     // 0..511
                const int m  = idx >> 2;           // row 0..127
                const int cc = idx & 3;            // 16B chunk in 64B row
                const uint32_t sw = tile_addr(m, cc);
                const size_t asrc = abase + (size_t)m * WIDTH + cc * 16;
                const size_t wsrc = wbase + (size_t)m * WIDTH + cc * 16;
                cp_async16(stb + OFF_A1 + sw, g_A1 + asrc);
                cp_async16(stb + OFF_A0 + sw, g_A0 + asrc);
                cp_async16(stb + OFF_W1 + sw, g_W1 + wsrc);
                cp_async16(stb + OFF_W0 + sw, g_W0 + wsrc);
            }
            cp_async_arrive_noinc(sbase + MB_FULL(s));
            pf.advance();
        }
        return;
    }

    // ================= CONSUMER WARPS (0..15) =================
    const int warp_moff = (wid & 3) * 32;
    const int warp_noff = (wid >> 2) * 32;

    int p11[2][4][4];
    int pm [2][4][4];
    int full_par[NSTAGE] = {0, 0, 0, 0, 0};

    Cursor cs; cs.init();

    for (int g = 0; g < NCHUNKS; g++) {
        const int s = g % NSTAGE;
        mbar_wait(sbase + MB_FULL(s), full_par[s]);
        full_par[s] ^= 1;

        if (cs.kc == 0) {
#pragma unroll
            for (int mi = 0; mi < 2; mi++)
#pragma unroll
                for (int ni = 0; ni < 4; ni++)
#pragma unroll
                    for (int q = 0; q < 4; q++) { p11[mi][ni][q] = 0; pm[mi][ni][q] = 0; }
        }

        const uint32_t stb = sbase + STAGE0_OFF + s * STAGE_BYTES;
        const int q4   = lane >> 3;
        const int rsub = lane & 7;

#pragma unroll
        for (int ks = 0; ks < 2; ks++) {
            const int arow  = warp_moff + (q4 & 1) * 8 + rsub;
            const int acc_c = ks * 2 + (q4 >> 1);
            const int bn    = warp_noff + (q4 >> 1) * 8 + rsub;
            const int bcc   = ks * 2 + (q4 & 1);

            uint32_t a1f[2][4], b1f[2][4];
#pragma unroll
            for (int mi = 0; mi < 2; mi++)
                ldsm4(a1f[mi][0], a1f[mi][1], a1f[mi][2], a1f[mi][3],
                      stb + OFF_A1 + tile_addr(arow + mi * 16, acc_c));
#pragma unroll
            for (int np = 0; np < 2; np++)
                ldsm4(b1f[np][0], b1f[np][1], b1f[np][2], b1f[np][3],
                      stb + OFF_W1 + tile_addr(bn + np * 16, bcc));
#pragma unroll
            for (int mi = 0; mi < 2; mi++)
#pragma unroll
                for (int ni = 0; ni < 4; ni++) {
                    const int np = ni >> 1, h = (ni & 1) * 2;
                    mma_s8(p11[mi][ni][0], p11[mi][ni][1], p11[mi][ni][2], p11[mi][ni][3],
                           a1f[mi][0], a1f[mi][1], a1f[mi][2], a1f[mi][3],
                           b1f[np][h], b1f[np][h + 1]);
                }
            uint32_t a0f[2][4];
#pragma unroll
            for (int mi = 0; mi < 2; mi++)
                ldsm4(a0f[mi][0], a0f[mi][1], a0f[mi][2], a0f[mi][3],
                      stb + OFF_A0 + tile_addr(arow + mi * 16, acc_c));
#pragma unroll
            for (int mi = 0; mi < 2; mi++)
#pragma unroll
                for (int ni = 0; ni < 4; ni++) {
                    const int np = ni >> 1, h = (ni & 1) * 2;
                    mma_s8(pm[mi][ni][0], pm[mi][ni][1], pm[mi][ni][2], pm[mi][ni][3],
                           a0f[mi][0], a0f[mi][1], a0f[mi][2], a0f[mi][3],
                           b1f[np][h], b1f[np][h + 1]);
                }
            uint32_t b0f[2][4];
#pragma unroll
            for (int np = 0; np < 2; np++)
                ldsm4(b0f[np][0], b0f[np][1], b0f[np][2], b0f[np][3],
                      stb + OFF_W0 + tile_addr(bn + np * 16, bcc));
#pragma unroll
            for (int mi = 0; mi < 2; mi++)
#pragma unroll
                for (int ni = 0; ni < 4; ni++) {
                    const int np = ni >> 1, h = (ni & 1) * 2;
                    mma_s8(pm[mi][ni][0], pm[mi][ni][1], pm[mi][ni][2], pm[mi][ni][3],
                           a1f[mi][0], a1f[mi][1], a1f[mi][2], a1f[mi][3],
                           b0f[np][h], b0f[np][h + 1]);
                }
        }

        // Early stage release: stage bytes are dead after the last LDSM above.
        // Only node-writeout chunks must hold the release until after the
        // global store + fence (the producer's RAW chain rides on it).
        const bool write_chunk = (cs.kc == 1) && (cs.e == cs.v - 1) && (cs.v != NNODES - 1);
        if (!write_chunk && lane == 0) mbar_arrive(sbase + MB_EMPTY(s));

        if (cs.kc == 1) {
            // ---- per-edge fold: dequant + bias + relu + accumulate in smem ----
            const float sc = sA_sm[cs.e] * g_sWfold[cs.w];
            const float* bp = bias + (size_t)cs.w * WIDTH + warp_noff + 2 * (lane & 3);
            const bool last  = (cs.e == cs.v - 1);
            const bool final_node = (cs.v == NNODES - 1);
            float mxloc = 0.f;
#pragma unroll
            for (int mi = 0; mi < 2; mi++)
#pragma unroll
                for (int ni = 0; ni < 4; ni++) {
                    const int i4 = mi * 4 + ni;
                    float4 sv;
                    if (cs.e == 0) sv = make_float4(0.f, 0.f, 0.f, 0.f);
                    else           sv = sumv[i4 * 512 + tid];
                    const float2 bb = *(const float2*)(bp + ni * 8);
                    float v0 = fmaf(16384.f, (float)p11[mi][ni][0], 128.f * (float)pm[mi][ni][0]) * sc + bb.x;
                    float v1 = fmaf(16384.f, (float)p11[mi][ni][1], 128.f * (float)pm[mi][ni][1]) * sc + bb.y;
                    float v2 = fmaf(16384.f, (float)p11[mi][ni][2], 128.f * (float)pm[mi][ni][2]) * sc + bb.x;
                    float v3 = fmaf(16384.f, (float)p11[mi][ni][3], 128.f * (float)pm[mi][ni][3]) * sc + bb.y;
                    sv.x += fmaxf(v0, 0.f);
                    sv.y += fmaxf(v1, 0.f);
                    sv.z += fmaxf(v2, 0.f);
                    sv.w += fmaxf(v3, 0.f);
                    if (last && final_node) {
                        const int col = warp_noff + 2 * (lane & 3) + ni * 8;
                        const int r0  = row0 + warp_moff + mi * 16 + (lane >> 2);
                        *(float2*)(out + (size_t)r0 * WIDTH + col)       = make_float2(sv.x, sv.y);
                        *(float2*)(out + (size_t)(r0 + 8) * WIDTH + col) = make_float2(sv.z, sv.w);
                    } else {
                        sumv[i4 * 512 + tid] = sv;
                        if (last) {
                            mxloc = fmaxf(mxloc, fmaxf(fmaxf(fabsf(sv.x), fabsf(sv.y)),
                                                       fmaxf(fabsf(sv.z), fabsf(sv.w))));
                        }
                    }
                }

            if (last && !final_node) {
                // ---- node end: block max -> quantize -> store int8 ----
                for (int o = 16; o; o >>= 1) mxloc = fmaxf(mxloc, __shfl_xor_sync(0xffffffffu, mxloc, o));
                if (lane == 0) red[wid] = mxloc;
                bar512();
                float mx = red[0];
#pragma unroll
                for (int i = 1; i < 16; i++) mx = fmaxf(mx, red[i]);
                const float sA = fmaxf(mx, 1e-30f);
                if (tid == 0) sA_sm[cs.v] = sA;   // later folds ordered via mbar chain
                const float inv = 16256.0f / sA;
                const size_t vb = (size_t)cs.v * (BATCH * WIDTH);
#pragma unroll
                for (int mi = 0; mi < 2; mi++)
#pragma unroll
                    for (int ni = 0; ni < 4; ni++) {
                        const float4 sv = sumv[(mi * 4 + ni) * 512 + tid];
                        const int col = warp_noff + 2 * (lane & 3) + ni * 8;
                        const int r0  = row0 + warp_moff + mi * 16 + (lane >> 2);
                        int h0, l0, h1, l1, h2, l2, h3, l3;
                        quant2(sv.x, inv, h0, l0); quant2(sv.y, inv, h1, l1);
                        quant2(sv.z, inv, h2, l2); quant2(sv.w, inv, h3, l3);
                        *(char2*)(g_A1 + vb + (size_t)r0 * WIDTH + col)       = make_char2((char)h0, (char)h1);
                        *(char2*)(g_A0 + vb + (size_t)r0 * WIDTH + col)       = make_char2((char)l0, (char)l1);
                        *(char2*)(g_A1 + vb + (size_t)(r0 + 8) * WIDTH + col) = make_char2((char)h2, (char)h3);
                        *(char2*)(g_A0 + vb + (size_t)(r0 + 8) * WIDTH + col) = make_char2((char)l2, (char)l3);
                    }
                __threadfence();
            }
        }

        if (write_chunk && lane == 0) mbar_arrive(sbase + MB_EMPTY(s));
        cs.advance();
    }
}

// ---------------- launch ----------------
extern "C" void kernel_launch(void* const* d_in, const int* in_sizes, int n_in,
                              void* d_out, int out_size) {
    const float* x = (const float*)d_in[0];
    const float* W = (const float*)d_in[1];
    const float* b = (const float*)d_in[2];
    float* out = (float*)d_out;

    cudaFuncSetAttribute(node_fused_kernel,
                         cudaFuncAttributeMaxDynamicSharedMemorySize, SMEM_TOTAL);

    w_prep_kernel<<<NEDGES, dim3(32, 8)>>>(W);
    node_fused_kernel<<<BATCH / BM, THREADS, SMEM_TOTAL>>>(x, b, out);
}

// round 15
// speedup vs baseline: 1.0645x; 1.0645x over previous
#include <cuda_runtime.h>
#include <cstdint>
#include <cstddef>

#define BATCH   16384
#define WIDTH   128
#define NNODES  12
#define NEDGES  66
#define NCHUNKS 132                        // sum over v of 2v (BK=64 chunks)

#define BM 128
#define THREADS 544                        // 16 consumer warps + 1 producer warp
#define TILE_BYTES (128 * 64)              // 128 rows x 64 int8 = 8 KB
#define STAGE_BYTES (4 * TILE_BYTES)       // A1, A0, W1, W0 = 32 KB
#define NSTAGE 4
#define SUM_OFF 1024
#define SUM_BYTES (8 * 512 * 16)           // 64 KB: float4 sumv[8][512]
#define STAGE0_OFF (SUM_OFF + SUM_BYTES)
#define SMEM_TOTAL (STAGE0_OFF + NSTAGE * STAGE_BYTES)   // 197632 B

#define MB_FULL(s)  ((s) * 8)              // 0..31
#define MB_EMPTY(s) (32 + (s) * 8)         // 32..63
#define SA_OFF  96                          // float sA_sm[12]
#define RED_OFF 160                         // float red[17]

#define OFF_A1 0
#define OFF_A0 TILE_BYTES
#define OFF_W1 (2 * TILE_BYTES)
#define OFF_W0 (3 * TILE_BYTES)

// ---------------- device scratch ----------------
__device__ int8_t g_A1[11u * BATCH * WIDTH];
__device__ int8_t g_A0[11u * BATCH * WIDTH];
__device__ int8_t g_W1[(size_t)NEDGES * WIDTH * WIDTH];   // [e][n][k] transposed
__device__ int8_t g_W0[(size_t)NEDGES * WIDTH * WIDTH];
__device__ float  g_sWfold[NEDGES];  // sW / 16256^2

// ---------------- PTX helpers ----------------
__device__ __forceinline__ uint32_t smem_u32(const void* p) {
    uint32_t a;
    asm("{ .reg .u64 t; cvta.to.shared.u64 t, %1; cvt.u32.u64 %0, t; }" : "=r"(a) : "l"(p));
    return a;
}
__device__ __forceinline__ void mbar_init(uint32_t a, uint32_t cnt) {
    asm volatile("mbarrier.init.shared.b64 [%0], %1;" :: "r"(a), "r"(cnt) : "memory");
}
__device__ __forceinline__ void mbar_arrive(uint32_t a) {
    asm volatile("mbarrier.arrive.shared.b64 _, [%0];" :: "r"(a) : "memory");
}
__device__ __forceinline__ void mbar_wait(uint32_t a, uint32_t parity) {
    asm volatile(
        "{\n\t.reg .pred P;\n\t"
        "WL%=:\n\t"
        "mbarrier.try_wait.parity.acquire.cta.shared::cta.b64 P, [%0], %1, 0x989680;\n\t"
        "@!P bra WL%=;\n\t}"
        :: "r"(a), "r"(parity) : "memory");
}
__device__ __forceinline__ void cp_async16(uint32_t dst, const void* src) {
    asm volatile("cp.async.cg.shared.global [%0], [%1], 16;" :: "r"(dst), "l"(src) : "memory");
}
__device__ __forceinline__ void cp_async_arrive_noinc(uint32_t mbar) {
    asm volatile("cp.async.mbarrier.arrive.noinc.shared.b64 [%0];" :: "r"(mbar) : "memory");
}
__device__ __forceinline__ void ldsm4(uint32_t& r0, uint32_t& r1, uint32_t& r2, uint32_t& r3,
                                      uint32_t addr) {
    asm volatile("ldmatrix.sync.aligned.m8n8.x4.shared.b16 {%0,%1,%2,%3}, [%4];"
                 : "=r"(r0), "=r"(r1), "=r"(r2), "=r"(r3) : "r"(addr));
}
__device__ __forceinline__ void mma_s8(int& d0, int& d1, int& d2, int& d3,
                                       uint32_t a0, uint32_t a1, uint32_t a2, uint32_t a3,
                                       uint32_t b0, uint32_t b1) {
    asm volatile(
        "mma.sync.aligned.m16n8k32.row.col.s32.s8.s8.s32 "
        "{%0,%1,%2,%3}, {%4,%5,%6,%7}, {%8,%9}, {%0,%1,%2,%3};"
        : "+r"(d0), "+r"(d1), "+r"(d2), "+r"(d3)
        : "r"(a0), "r"(a1), "r"(a2), "r"(a3), "r"(b0), "r"(b1));
}
__device__ __forceinline__ void bar512() {
    asm volatile("bar.sync 1, 512;" ::: "memory");
}

// swizzled tile address: 128 rows x 64B, 2 rows per 128B line, XOR by line index
__device__ __forceinline__ uint32_t tile_addr(int m, int cc) {
    return (uint32_t)((m >> 1) * 128 + (((((m & 1) << 2) | cc) ^ ((m >> 1) & 7)) << 4));
}

__device__ __forceinline__ void quant2(float h, float inv, int& hi, int& lo) {
    float qf = rintf(h * inv);                 // |qf| <= 16256
    float f1 = rintf(qf * 0.0078125f);         // /128
    hi = (int)f1;
    lo = (int)(qf - 128.0f * f1);              // in [-64, 64]
}

// ---------------- W preprocessing: max + transpose + quantize (one kernel) ----------------
__global__ void w_prep_kernel(const float* __restrict__ W) {
    __shared__ float t[32][33];
    __shared__ float red[8];
    __shared__ float qs_sm;
    const int e = blockIdx.x;
    const int tx = threadIdx.x, ty = threadIdx.y;      // 32 x 8
    const int tid = ty * 32 + tx;
    const float* Wb = W + (size_t)e * WIDTH * WIDTH;

    float mx = 0.f;
    for (int i = tid; i < WIDTH * WIDTH; i += 256) mx = fmaxf(mx, fabsf(Wb[i]));
    for (int o = 16; o; o >>= 1) mx = fmaxf(mx, __shfl_xor_sync(0xffffffffu, mx, o));
    if (tx == 0) red[ty] = mx;
    __syncthreads();
    if (tid == 0) {
        mx = red[0];
#pragma unroll
        for (int i = 1; i < 8; i++) mx = fmaxf(mx, red[i]);
        mx = fmaxf(mx, 1e-30f);
        qs_sm = 16256.0f / mx;
        g_sWfold[e] = mx / (16256.0f * 16256.0f);
    }
    __syncthreads();
    const float qs = qs_sm;
    int8_t* H1 = g_W1 + (size_t)e * WIDTH * WIDTH;
    int8_t* H0 = g_W0 + (size_t)e * WIDTH * WIDTH;

    for (int ti = 0; ti < 16; ti++) {
        const int kt = (ti & 3) * 32;
        const int nt = (ti >> 2) * 32;
#pragma unroll
        for (int r = 0; r < 32; r += 8)
            t[ty + r][tx] = Wb[(kt + ty + r) * WIDTH + nt + tx];
        __syncthreads();
#pragma unroll
        for (int r = 0; r < 32; r += 8) {
            const int n = nt + ty + r;
            float v = t[tx][ty + r];
            int hi, lo;
            quant2(v, qs, hi, lo);
            H1[n * WIDTH + kt + tx] = (int8_t)hi;
            H0[n * WIDTH + kt + tx] = (int8_t)lo;
        }
        __syncthreads();
    }
}

// chunk cursor
struct Cursor {
    int v, e, kc, w;
    __device__ __forceinline__ void init() { v = 1; e = 0; kc = 0; w = 0; }
    __device__ __forceinline__ void advance() {
        if (kc == 0) { kc = 1; return; }
        kc = 0; e++; w++;
        if (e == v) { e = 0; v++; w = v * (v - 1) / 2; }
    }
};

// ---------------- fused kernel ----------------
__global__ void __launch_bounds__(THREADS, 1) node_fused_kernel(
    const float* __restrict__ x,
    const float* __restrict__ bias,
    float* __restrict__ out)
{
    extern __shared__ __align__(1024) char smem[];
    const uint32_t sbase = smem_u32(smem);
    float*  sA_sm = (float*)(smem + SA_OFF);
    float*  red   = (float*)(smem + RED_OFF);
    float4* sumv  = (float4*)(smem + SUM_OFF);

    const int tid  = threadIdx.x;
    const int lane = tid & 31;
    const int wid  = tid >> 5;
    const int row0 = blockIdx.x * BM;

    if (tid == 0) {
#pragma unroll
        for (int s = 0; s < NSTAGE; s++) {
            mbar_init(sbase + MB_FULL(s), 32);
            mbar_init(sbase + MB_EMPTY(s), 16);
        }
    }

    // ---- x quantization for this CTA's 128 rows ----
    {
        const float4* xs = (const float4*)(x + (size_t)row0 * WIDTH);
        float mx = 0.f;
        for (int i = tid; i < 4096; i += THREADS) {
            float4 v = xs[i];
            mx = fmaxf(mx, fmaxf(fmaxf(fabsf(v.x), fabsf(v.y)), fmaxf(fabsf(v.z), fabsf(v.w))));
        }
        for (int o = 16; o; o >>= 1) mx = fmaxf(mx, __shfl_xor_sync(0xffffffffu, mx, o));
        if (lane == 0) red[wid] = mx;
        __syncthreads();
        mx = red[0];
#pragma unroll
        for (int i = 1; i < 17; i++) mx = fmaxf(mx, red[i]);
        const float sA = fmaxf(mx, 1e-30f);
        if (tid == 0) sA_sm[0] = sA;
        const float inv = 16256.0f / sA;
        for (int i = tid; i < 4096; i += THREADS) {
            float4 v = xs[i];
            int h0, l0, h1, l1, h2, l2, h3, l3;
            quant2(v.x, inv, h0, l0); quant2(v.y, inv, h1, l1);
            quant2(v.z, inv, h2, l2); quant2(v.w, inv, h3, l3);
            *(char4*)(g_A1 + (size_t)row0 * WIDTH + (size_t)i * 4) =
                make_char4((char)h0, (char)h1, (char)h2, (char)h3);
            *(char4*)(g_A0 + (size_t)row0 * WIDTH + (size_t)i * 4) =
                make_char4((char)l0, (char)l1, (char)l2, (char)l3);
        }
    }
    __syncthreads();   // x data + barriers + sA_sm[0] visible

    if (wid == 16) {
        // ================= PRODUCER WARP =================
        Cursor pf; pf.init();
        int empty_par[NSTAGE] = {0, 0, 0, 0};
        for (int g = 0; g < NCHUNKS; g++) {
            const int s = g & 3;
            if (g >= NSTAGE) {
                mbar_wait(sbase + MB_EMPTY(s), empty_par[s]);
                empty_par[s] ^= 1;
            }
            // RAW hazard (NSTAGE=4, v=1): chunk 4 reads node-1 output written at
            // chunk 1; the g-4 back-wait only covers chunk 0. Wait chunk 1 done.
            if (g == 4) mbar_wait(sbase + MB_EMPTY(1), 0);
            const uint32_t stb = sbase + STAGE0_OFF + s * STAGE_BYTES;
            const size_t abase = (size_t)pf.e * (BATCH * WIDTH) + (size_t)row0 * WIDTH + pf.kc * 64;
            const size_t wbase = (size_t)pf.w * (WIDTH * WIDTH) + pf.kc * 64;
#pragma unroll
            for (int j = 0; j < 16; j++) {
                const int idx = j * 32 + lane;     // 0..511
                const int m  = idx >> 2;           // row 0..127
                const int cc = idx & 3;            // 16B chunk in 64B row
                const uint32_t sw = tile_addr(m, cc);
                const size_t asrc = abase + (size_t)m * WIDTH + cc * 16;
                const size_t wsrc = wbase + (size_t)m * WIDTH + cc * 16;
                cp_async16(stb + OFF_A1 + sw, g_A1 + asrc);
                cp_async16(stb + OFF_A0 + sw, g_A0 + asrc);
                cp_async16(stb + OFF_W1 + sw, g_W1 + wsrc);
                cp_async16(stb + OFF_W0 + sw, g_W0 + wsrc);
            }
            cp_async_arrive_noinc(sbase + MB_FULL(s));
            pf.advance();
        }
        return;
    }

    // ================= CONSUMER WARPS (0..15) =================
    const int warp_moff = (wid & 3) * 32;
    const int warp_noff = (wid >> 2) * 32;

    int p11[2][4][4];
    int pm [2][4][4];
    int full_par[NSTAGE] = {0, 0, 0, 0};

    Cursor cs; cs.init();

    for (int g = 0; g < NCHUNKS; g++) {
        const int s = g & 3;
        mbar_wait(sbase + MB_FULL(s), full_par[s]);
        full_par[s] ^= 1;

        if (cs.kc == 0) {
#pragma unroll
            for (int mi = 0; mi < 2; mi++)
#pragma unroll
                for (int ni = 0; ni < 4; ni++)
#pragma unroll
                    for (int q = 0; q < 4; q++) { p11[mi][ni][q] = 0; pm[mi][ni][q] = 0; }
        }

        const uint32_t stb = sbase + STAGE0_OFF + s * STAGE_BYTES;
        const int q4   = lane >> 3;
        const int rsub = lane & 7;

#pragma unroll
        for (int ks = 0; ks < 2; ks++) {
            const int arow  = warp_moff + (q4 & 1) * 8 + rsub;
            const int acc_c = ks * 2 + (q4 >> 1);
            const int bn    = warp_noff + (q4 >> 1) * 8 + rsub;
            const int bcc   = ks * 2 + (q4 & 1);

            uint32_t a1f[2][4], b1f[2][4];
#pragma unroll
            for (int mi = 0; mi < 2; mi++)
                ldsm4(a1f[mi][0], a1f[mi][1], a1f[mi][2], a1f[mi][3],
                      stb + OFF_A1 + tile_addr(arow + mi * 16, acc_c));
#pragma unroll
            for (int np = 0; np < 2; np++)
                ldsm4(b1f[np][0], b1f[np][1], b1f[np][2], b1f[np][3],
                      stb + OFF_W1 + tile_addr(bn + np * 16, bcc));
#pragma unroll
            for (int mi = 0; mi < 2; mi++)
#pragma unroll
                for (int ni = 0; ni < 4; ni++) {
                    const int np = ni >> 1, h = (ni & 1) * 2;
                    mma_s8(p11[mi][ni][0], p11[mi][ni][1], p11[mi][ni][2], p11[mi][ni][3],
                           a1f[mi][0], a1f[mi][1], a1f[mi][2], a1f[mi][3],
                           b1f[np][h], b1f[np][h + 1]);
                }
            uint32_t a0f[2][4];
#pragma unroll
            for (int mi = 0; mi < 2; mi++)
                ldsm4(a0f[mi][0], a0f[mi][1], a0f[mi][2], a0f[mi][3],
                      stb + OFF_A0 + tile_addr(arow + mi * 16, acc_c));
#pragma unroll
            for (int mi = 0; mi < 2; mi++)
#pragma unroll
                for (int ni = 0; ni < 4; ni++) {
                    const int np = ni >> 1, h = (ni & 1) * 2;
                    mma_s8(pm[mi][ni][0], pm[mi][ni][1], pm[mi][ni][2], pm[mi][ni][3],
                           a0f[mi][0], a0f[mi][1], a0f[mi][2], a0f[mi][3],
                           b1f[np][h], b1f[np][h + 1]);
                }
            uint32_t b0f[2][4];
#pragma unroll
            for (int np = 0; np < 2; np++)
                ldsm4(b0f[np][0], b0f[np][1], b0f[np][2], b0f[np][3],
                      stb + OFF_W0 + tile_addr(bn + np * 16, bcc));
#pragma unroll
            for (int mi = 0; mi < 2; mi++)
#pragma unroll
                for (int ni = 0; ni < 4; ni++) {
                    const int np = ni >> 1, h = (ni & 1) * 2;
                    mma_s8(pm[mi][ni][0], pm[mi][ni][1], pm[mi][ni][2], pm[mi][ni][3],
                           a1f[mi][0], a1f[mi][1], a1f[mi][2], a1f[mi][3],
                           b0f[np][h], b0f[np][h + 1]);
                }
        }

        // Early stage release: stage bytes are dead after the last LDSM above.
        // Node-writeout chunks keep the late release (producer RAW chain).
        const bool write_chunk = (cs.kc == 1) && (cs.e == cs.v - 1) && (cs.v != NNODES - 1);
        if (!write_chunk && lane == 0) mbar_arrive(sbase + MB_EMPTY(s));

        if (cs.kc == 1) {
            // ---- per-edge fold: dequant + bias + relu + accumulate in smem ----
            const float sc = sA_sm[cs.e] * g_sWfold[cs.w];
            const float* bp = bias + (size_t)cs.w * WIDTH + warp_noff + 2 * (lane & 3);
            const bool last  = (cs.e == cs.v - 1);
            const bool final_node = (cs.v == NNODES - 1);
            float mxloc = 0.f;
#pragma unroll
            for (int mi = 0; mi < 2; mi++)
#pragma unroll
                for (int ni = 0; ni < 4; ni++) {
                    const int i4 = mi * 4 + ni;
                    float4 sv;
                    if (cs.e == 0) sv = make_float4(0.f, 0.f, 0.f, 0.f);
                    else           sv = sumv[i4 * 512 + tid];
                    const float2 bb = *(const float2*)(bp + ni * 8);
                    float v0 = fmaf(16384.f, (float)p11[mi][ni][0], 128.f * (float)pm[mi][ni][0]) * sc + bb.x;
                    float v1 = fmaf(16384.f, (float)p11[mi][ni][1], 128.f * (float)pm[mi][ni][1]) * sc + bb.y;
                    float v2 = fmaf(16384.f, (float)p11[mi][ni][2], 128.f * (float)pm[mi][ni][2]) * sc + bb.x;
                    float v3 = fmaf(16384.f, (float)p11[mi][ni][3], 128.f * (float)pm[mi][ni][3]) * sc + bb.y;
                    sv.x += fmaxf(v0, 0.f);
                    sv.y += fmaxf(v1, 0.f);
                    sv.z += fmaxf(v2, 0.f);
                    sv.w += fmaxf(v3, 0.f);
                    if (last && final_node) {
                        const int col = warp_noff + 2 * (lane & 3) + ni * 8;
                        const int r0  = row0 + warp_moff + mi * 16 + (lane >> 2);
                        *(float2*)(out + (size_t)r0 * WIDTH + col)       = make_float2(sv.x, sv.y);
                        *(float2*)(out + (size_t)(r0 + 8) * WIDTH + col) = make_float2(sv.z, sv.w);
                    } else {
                        sumv[i4 * 512 + tid] = sv;
                        if (last) {
                            mxloc = fmaxf(mxloc, fmaxf(fmaxf(fabsf(sv.x), fabsf(sv.y)),
                                                       fmaxf(fabsf(sv.z), fabsf(sv.w))));
                        }
                    }
                }

            if (last && !final_node) {
                // ---- node end: block max -> quantize -> store int8 ----
                for (int o = 16; o; o >>= 1) mxloc = fmaxf(mxloc, __shfl_xor_sync(0xffffffffu, mxloc, o));
                if (lane == 0) red[wid] = mxloc;
                bar512();
                float mx = red[0];
#pragma unroll
                for (int i = 1; i < 16; i++) mx = fmaxf(mx, red[i]);
                const float sA = fmaxf(mx, 1e-30f);
                if (tid == 0) sA_sm[cs.v] = sA;   // later folds ordered via mbar chain
                const float inv = 16256.0f / sA;
                const size_t vb = (size_t)cs.v * (BATCH * WIDTH);
#pragma unroll
                for (int mi = 0; mi < 2; mi++)
#pragma unroll
                    for (int ni = 0; ni < 4; ni++) {
                        const float4 sv = sumv[(mi * 4 + ni) * 512 + tid];
                        const int col = warp_noff + 2 * (lane & 3) + ni * 8;
                        const int r0  = row0 + warp_moff + mi * 16 + (lane >> 2);
                        int h0, l0, h1, l1, h2, l2, h3, l3;
                        quant2(sv.x, inv, h0, l0); quant2(sv.y, inv, h1, l1);
                        quant2(sv.z, inv, h2, l2); quant2(sv.w, inv, h3, l3);
                        *(char2*)(g_A1 + vb + (size_t)r0 * WIDTH + col)       = make_char2((char)h0, (char)h1);
                        *(char2*)(g_A0 + vb + (size_t)r0 * WIDTH + col)       = make_char2((char)l0, (char)l1);
                        *(char2*)(g_A1 + vb + (size_t)(r0 + 8) * WIDTH + col) = make_char2((char)h2, (char)h3);
                        *(char2*)(g_A0 + vb + (size_t)(r0 + 8) * WIDTH + col) = make_char2((char)l2, (char)l3);
                    }
                __threadfence();
            }
        }

        if (write_chunk && lane == 0) mbar_arrive(sbase + MB_EMPTY(s));
        cs.advance();
    }
}

// ---------------- launch ----------------
extern "C" void kernel_launch(void* const* d_in, const int* in_sizes, int n_in,
                              void* d_out, int out_size) {
    const float* x = (const float*)d_in[0];
    const float* W = (const float*)d_in[1];
    const float* b = (const float*)d_in[2];
    float* out = (float*)d_out;

    cudaFuncSetAttribute(node_fused_kernel,
                         cudaFuncAttributeMaxDynamicSharedMemorySize, SMEM_TOTAL);

    w_prep_kernel<<<NEDGES, dim3(32, 8)>>>(W);
    node_fused_kernel<<<BATCH / BM, THREADS, SMEM_TOTAL>>>(x, b, out);
}

// round 16
// speedup vs baseline: 1.3274x; 1.2470x over previous
#include <cuda_runtime.h>
#include <cstdint>
#include <cstddef>

#define BATCH   16384
#define WIDTH   128
#define NNODES  12
#define NEDGES  66
#define NCHUNKS 132                        // sum over v of 2v (BK=64 chunks)

#define BM 128
#define THREADS 544                        // 16 consumer warps + 1 producer warp
#define TILE_BYTES (128 * 64)              // 128 rows x 64 int8 = 8 KB
#define STAGE_BYTES (4 * TILE_BYTES)       // A1, A0, W1, W0 = 32 KB
#define NSTAGE 4
#define SUM_OFF 1024
#define SUM_BYTES (8 * 512 * 16)           // 64 KB: float4 sumv[8][512]
#define STAGE0_OFF (SUM_OFF + SUM_BYTES)
#define SMEM_TOTAL (STAGE0_OFF + NSTAGE * STAGE_BYTES)   // 197632 B

#define MB_FULL(s)  ((s) * 8)              // 0..31
#define MB_EMPTY(s) (32 + (s) * 8)         // 32..63
#define SA_OFF  96                          // float sA_sm[12]
#define RED_OFF 160                         // float red[17]

#define OFF_A1 0
#define OFF_A0 TILE_BYTES
#define OFF_W1 (2 * TILE_BYTES)
#define OFF_W0 (3 * TILE_BYTES)

// ---------------- device scratch ----------------
__device__ int8_t g_A1[11u * BATCH * WIDTH];
__device__ int8_t g_A0[11u * BATCH * WIDTH];
__device__ int8_t g_W1[(size_t)NEDGES * WIDTH * WIDTH];   // [e][n][k] transposed
__device__ int8_t g_W0[(size_t)NEDGES * WIDTH * WIDTH];
__device__ float  g_sWfold[NEDGES];  // sW / 16256^2

// ---------------- PTX helpers ----------------
__device__ __forceinline__ uint32_t smem_u32(const void* p) {
    uint32_t a;
    asm("{ .reg .u64 t; cvta.to.shared.u64 t, %1; cvt.u32.u64 %0, t; }" : "=r"(a) : "l"(p));
    return a;
}
__device__ __forceinline__ void mbar_init(uint32_t a, uint32_t cnt) {
    asm volatile("mbarrier.init.shared.b64 [%0], %1;" :: "r"(a), "r"(cnt) : "memory");
}
__device__ __forceinline__ void mbar_arrive(uint32_t a) {
    asm volatile("mbarrier.arrive.shared.b64 _, [%0];" :: "r"(a) : "memory");
}
__device__ __forceinline__ void mbar_wait(uint32_t a, uint32_t parity) {
    asm volatile(
        "{\n\t.reg .pred P;\n\t"
        "WL%=:\n\t"
        "mbarrier.try_wait.parity.acquire.cta.shared::cta.b64 P, [%0], %1, 0x989680;\n\t"
        "@!P bra WL%=;\n\t}"
        :: "r"(a), "r"(parity) : "memory");
}
__device__ __forceinline__ void cp_async16(uint32_t dst, const void* src) {
    asm volatile("cp.async.cg.shared.global [%0], [%1], 16;" :: "r"(dst), "l"(src) : "memory");
}
__device__ __forceinline__ void cp_async_arrive_noinc(uint32_t mbar) {
    asm volatile("cp.async.mbarrier.arrive.noinc.shared.b64 [%0];" :: "r"(mbar) : "memory");
}
__device__ __forceinline__ void ldsm4(uint32_t& r0, uint32_t& r1, uint32_t& r2, uint32_t& r3,
                                      uint32_t addr) {
    asm volatile("ldmatrix.sync.aligned.m8n8.x4.shared.b16 {%0,%1,%2,%3}, [%4];"
                 : "=r"(r0), "=r"(r1), "=r"(r2), "=r"(r3) : "r"(addr));
}
__device__ __forceinline__ void mma_s8(int& d0, int& d1, int& d2, int& d3,
                                       uint32_t a0, uint32_t a1, uint32_t a2, uint32_t a3,
                                       uint32_t b0, uint32_t b1) {
    asm volatile(
        "mma.sync.aligned.m16n8k32.row.col.s32.s8.s8.s32 "
        "{%0,%1,%2,%3}, {%4,%5,%6,%7}, {%8,%9}, {%0,%1,%2,%3};"
        : "+r"(d0), "+r"(d1), "+r"(d2), "+r"(d3)
        : "r"(a0), "r"(a1), "r"(a2), "r"(a3), "r"(b0), "r"(b1));
}
__device__ __forceinline__ void bar512() {
    asm volatile("bar.sync 1, 512;" ::: "memory");
}

// swizzled tile address: 128 rows x 64B, 2 rows per 128B line, XOR by line index
__device__ __forceinline__ uint32_t tile_addr(int m, int cc) {
    return (uint32_t)((m >> 1) * 128 + (((((m & 1) << 2) | cc) ^ ((m >> 1) & 7)) << 4));
}

__device__ __forceinline__ void quant2(float h, float inv, int& hi, int& lo) {
    float qf = rintf(h * inv);                 // |qf| <= 16256
    float f1 = rintf(qf * 0.0078125f);         // /128
    hi = (int)f1;
    lo = (int)(qf - 128.0f * f1);              // in [-64, 64]
}

// ---------------- W preprocessing: max + transpose + quantize (one kernel) ----------------
__global__ void w_prep_kernel(const float* __restrict__ W) {
    __shared__ float t[32][33];
    __shared__ float red[8];
    __shared__ float qs_sm;
    const int e = blockIdx.x;
    const int tx = threadIdx.x, ty = threadIdx.y;      // 32 x 8
    const int tid = ty * 32 + tx;
    const float* Wb = W + (size_t)e * WIDTH * WIDTH;

    float mx = 0.f;
    for (int i = tid; i < WIDTH * WIDTH; i += 256) mx = fmaxf(mx, fabsf(Wb[i]));
    for (int o = 16; o; o >>= 1) mx = fmaxf(mx, __shfl_xor_sync(0xffffffffu, mx, o));
    if (tx == 0) red[ty] = mx;
    __syncthreads();
    if (tid == 0) {
        mx = red[0];
#pragma unroll
        for (int i = 1; i < 8; i++) mx = fmaxf(mx, red[i]);
        mx = fmaxf(mx, 1e-30f);
        qs_sm = 16256.0f / mx;
        g_sWfold[e] = mx / (16256.0f * 16256.0f);
    }
    __syncthreads();
    const float qs = qs_sm;
    int8_t* H1 = g_W1 + (size_t)e * WIDTH * WIDTH;
    int8_t* H0 = g_W0 + (size_t)e * WIDTH * WIDTH;

    for (int ti = 0; ti < 16; ti++) {
        const int kt = (ti & 3) * 32;
        const int nt = (ti >> 2) * 32;
#pragma unroll
        for (int r = 0; r < 32; r += 8)
            t[ty + r][tx] = Wb[(kt + ty + r) * WIDTH + nt + tx];
        __syncthreads();
#pragma unroll
        for (int r = 0; r < 32; r += 8) {
            const int n = nt + ty + r;
            float v = t[tx][ty + r];
            int hi, lo;
            quant2(v, qs, hi, lo);
            H1[n * WIDTH + kt + tx] = (int8_t)hi;
            H0[n * WIDTH + kt + tx] = (int8_t)lo;
        }
        __syncthreads();
    }
}

// chunk cursor
struct Cursor {
    int v, e, kc, w;
    __device__ __forceinline__ void init() { v = 1; e = 0; kc = 0; w = 0; }
    __device__ __forceinline__ void advance() {
        if (kc == 0) { kc = 1; return; }
        kc = 0; e++; w++;
        if (e == v) { e = 0; v++; w = v * (v - 1) / 2; }
    }
};

// ---------------- fused kernel ----------------
__global__ void __launch_bounds__(THREADS, 1) node_fused_kernel(
    const float* __restrict__ x,
    const float* __restrict__ bias,
    float* __restrict__ out)
{
    extern __shared__ __align__(1024) char smem[];
    const uint32_t sbase = smem_u32(smem);
    float*  sA_sm = (float*)(smem + SA_OFF);
    float*  red   = (float*)(smem + RED_OFF);
    float4* sumv  = (float4*)(smem + SUM_OFF);

    const int tid  = threadIdx.x;
    const int lane = tid & 31;
    const int wid  = tid >> 5;
    const int row0 = blockIdx.x * BM;

    if (tid == 0) {
#pragma unroll
        for (int s = 0; s < NSTAGE; s++) {
            mbar_init(sbase + MB_FULL(s), 32);
            mbar_init(sbase + MB_EMPTY(s), 16);
        }
    }

    // ---- x quantization for this CTA's 128 rows ----
    {
        const float4* xs = (const float4*)(x + (size_t)row0 * WIDTH);
        float mx = 0.f;
        for (int i = tid; i < 4096; i += THREADS) {
            float4 v = xs[i];
            mx = fmaxf(mx, fmaxf(fmaxf(fabsf(v.x), fabsf(v.y)), fmaxf(fabsf(v.z), fabsf(v.w))));
        }
        for (int o = 16; o; o >>= 1) mx = fmaxf(mx, __shfl_xor_sync(0xffffffffu, mx, o));
        if (lane == 0) red[wid] = mx;
        __syncthreads();
        mx = red[0];
#pragma unroll
        for (int i = 1; i < 17; i++) mx = fmaxf(mx, red[i]);
        const float sA = fmaxf(mx, 1e-30f);
        if (tid == 0) sA_sm[0] = sA;
        const float inv = 16256.0f / sA;
        for (int i = tid; i < 4096; i += THREADS) {
            float4 v = xs[i];
            int h0, l0, h1, l1, h2, l2, h3, l3;
            quant2(v.x, inv, h0, l0); quant2(v.y, inv, h1, l1);
            quant2(v.z, inv, h2, l2); quant2(v.w, inv, h3, l3);
            *(char4*)(g_A1 + (size_t)row0 * WIDTH + (size_t)i * 4) =
                make_char4((char)h0, (char)h1, (char)h2, (char)h3);
            *(char4*)(g_A0 + (size_t)row0 * WIDTH + (size_t)i * 4) =
                make_char4((char)l0, (char)l1, (char)l2, (char)l3);
        }
    }
    __syncthreads();   // x data + barriers + sA_sm[0] visible

    if (wid == 16) {
        // ================= PRODUCER WARP =================
        Cursor pf; pf.init();
        int empty_par[NSTAGE] = {0, 0, 0, 0};
        for (int g = 0; g < NCHUNKS; g++) {
            const int s = g & 3;
            if (g >= NSTAGE) {
                mbar_wait(sbase + MB_EMPTY(s), empty_par[s]);
                empty_par[s] ^= 1;
            }
            // RAW hazard (NSTAGE=4, v=1): chunk 4 reads node-1 output written at
            // chunk 1; the g-4 back-wait only covers chunk 0. Wait chunk 1 done.
            if (g == 4) mbar_wait(sbase + MB_EMPTY(1), 0);
            const uint32_t stb = sbase + STAGE0_OFF + s * STAGE_BYTES;
            const size_t abase = (size_t)pf.e * (BATCH * WIDTH) + (size_t)row0 * WIDTH + pf.kc * 64;
            const size_t wbase = (size_t)pf.w * (WIDTH * WIDTH) + pf.kc * 64;
#pragma unroll
            for (int j = 0; j < 16; j++) {
                const int idx = j * 32 + lane;     // 0..511
                const int m  = idx >> 2;           // row 0..127
                const int cc = idx & 3;            // 16B chunk in 64B row
                const uint32_t sw = tile_addr(m, cc);
                const size_t asrc = abase + (size_t)m * WIDTH + cc * 16;
                const size_t wsrc = wbase + (size_t)m * WIDTH + cc * 16;
                cp_async16(stb + OFF_A1 + sw, g_A1 + asrc);
                cp_async16(stb + OFF_A0 + sw, g_A0 + asrc);
                cp_async16(stb + OFF_W1 + sw, g_W1 + wsrc);
                cp_async16(stb + OFF_W0 + sw, g_W0 + wsrc);
            }
            cp_async_arrive_noinc(sbase + MB_FULL(s));
            pf.advance();
        }
        return;
    }

    // ================= CONSUMER WARPS (0..15) =================
    const int warp_moff = (wid & 3) * 32;
    const int warp_noff = (wid >> 2) * 32;

    int p11[2][4][4];
    int pm [2][4][4];
    int full_par[NSTAGE] = {0, 0, 0, 0};

    Cursor cs; cs.init();

    for (int g = 0; g < NCHUNKS; g++) {
        const int s = g & 3;
        mbar_wait(sbase + MB_FULL(s), full_par[s]);
        full_par[s] ^= 1;

        if (cs.kc == 0) {
#pragma unroll
            for (int mi = 0; mi < 2; mi++)
#pragma unroll
                for (int ni = 0; ni < 4; ni++)
#pragma unroll
                    for (int q = 0; q < 4; q++) { p11[mi][ni][q] = 0; pm[mi][ni][q] = 0; }
        }

        const uint32_t stb = sbase + STAGE0_OFF + s * STAGE_BYTES;
        const int q4   = lane >> 3;
        const int rsub = lane & 7;

#pragma unroll
        for (int ks = 0; ks < 2; ks++) {
            const int arow  = warp_moff + (q4 & 1) * 8 + rsub;
            const int acc_c = ks * 2 + (q4 >> 1);
            const int bn    = warp_noff + (q4 >> 1) * 8 + rsub;
            const int bcc   = ks * 2 + (q4 & 1);

            uint32_t a1f[2][4], b1f[2][4];
#pragma unroll
            for (int mi = 0; mi < 2; mi++)
                ldsm4(a1f[mi][0], a1f[mi][1], a1f[mi][2], a1f[mi][3],
                      stb + OFF_A1 + tile_addr(arow + mi * 16, acc_c));
#pragma unroll
            for (int np = 0; np < 2; np++)
                ldsm4(b1f[np][0], b1f[np][1], b1f[np][2], b1f[np][3],
                      stb + OFF_W1 + tile_addr(bn + np * 16, bcc));
#pragma unroll
            for (int mi = 0; mi < 2; mi++)
#pragma unroll
                for (int ni = 0; ni < 4; ni++) {
                    const int np = ni >> 1, h = (ni & 1) * 2;
                    mma_s8(p11[mi][ni][0], p11[mi][ni][1], p11[mi][ni][2], p11[mi][ni][3],
                           a1f[mi][0], a1f[mi][1], a1f[mi][2], a1f[mi][3],
                           b1f[np][h], b1f[np][h + 1]);
                }
            uint32_t a0f[2][4];
#pragma unroll
            for (int mi = 0; mi < 2; mi++)
                ldsm4(a0f[mi][0], a0f[mi][1], a0f[mi][2], a0f[mi][3],
                      stb + OFF_A0 + tile_addr(arow + mi * 16, acc_c));
#pragma unroll
            for (int mi = 0; mi < 2; mi++)
#pragma unroll
                for (int ni = 0; ni < 4; ni++) {
                    const int np = ni >> 1, h = (ni & 1) * 2;
                    mma_s8(pm[mi][ni][0], pm[mi][ni][1], pm[mi][ni][2], pm[mi][ni][3],
                           a0f[mi][0], a0f[mi][1], a0f[mi][2], a0f[mi][3],
                           b1f[np][h], b1f[np][h + 1]);
                }
            uint32_t b0f[2][4];
#pragma unroll
            for (int np = 0; np < 2; np++)
                ldsm4(b0f[np][0], b0f[np][1], b0f[np][2], b0f[np][3],
                      stb + OFF_W0 + tile_addr(bn + np * 16, bcc));
#pragma unroll
            for (int mi = 0; mi < 2; mi++)
#pragma unroll
                for (int ni = 0; ni < 4; ni++) {
                    const int np = ni >> 1, h = (ni & 1) * 2;
                    mma_s8(pm[mi][ni][0], pm[mi][ni][1], pm[mi][ni][2], pm[mi][ni][3],
                           a1f[mi][0], a1f[mi][1], a1f[mi][2], a1f[mi][3],
                           b0f[np][h], b0f[np][h + 1]);
                }
        }

        if (cs.kc == 1) {
            // ---- per-edge fold: dequant + bias + relu + accumulate in smem ----
            const float sc = sA_sm[cs.e] * g_sWfold[cs.w];
            const float* bp = bias + (size_t)cs.w * WIDTH + warp_noff + 2 * (lane & 3);
            const bool last  = (cs.e == cs.v - 1);
            const bool final_node = (cs.v == NNODES - 1);
            float mxloc = 0.f;
#pragma unroll
            for (int mi = 0; mi < 2; mi++)
#pragma unroll
                for (int ni = 0; ni < 4; ni++) {
                    const int i4 = mi * 4 + ni;
                    float4 sv;
                    if (cs.e == 0) sv = make_float4(0.f, 0.f, 0.f, 0.f);
                    else           sv = sumv[i4 * 512 + tid];
                    const float2 bb = *(const float2*)(bp + ni * 8);
                    float v0 = fmaf(16384.f, (float)p11[mi][ni][0], 128.f * (float)pm[mi][ni][0]) * sc + bb.x;
                    float v1 = fmaf(16384.f, (float)p11[mi][ni][1], 128.f * (float)pm[mi][ni][1]) * sc + bb.y;
                    float v2 = fmaf(16384.f, (float)p11[mi][ni][2], 128.f * (float)pm[mi][ni][2]) * sc + bb.x;
                    float v3 = fmaf(16384.f, (float)p11[mi][ni][3], 128.f * (float)pm[mi][ni][3]) * sc + bb.y;
                    sv.x += fmaxf(v0, 0.f);
                    sv.y += fmaxf(v1, 0.f);
                    sv.z += fmaxf(v2, 0.f);
                    sv.w += fmaxf(v3, 0.f);
                    if (last && final_node) {
                        const int col = warp_noff + 2 * (lane & 3) + ni * 8;
                        const int r0  = row0 + warp_moff + mi * 16 + (lane >> 2);
                        *(float2*)(out + (size_t)r0 * WIDTH + col)       = make_float2(sv.x, sv.y);
                        *(float2*)(out + (size_t)(r0 + 8) * WIDTH + col) = make_float2(sv.z, sv.w);
                    } else {
                        sumv[i4 * 512 + tid] = sv;
                        if (last) {
                            mxloc = fmaxf(mxloc, fmaxf(fmaxf(fabsf(sv.x), fabsf(sv.y)),
                                                       fmaxf(fabsf(sv.z), fabsf(sv.w))));
                        }
                    }
                }

            if (last && !final_node) {
                // ---- node end: block max -> quantize -> store int8 ----
                for (int o = 16; o; o >>= 1) mxloc = fmaxf(mxloc, __shfl_xor_sync(0xffffffffu, mxloc, o));
                if (lane == 0) red[wid] = mxloc;
                bar512();
                // every thread computes the block max locally (no second barrier)
                float mx = red[0];
#pragma unroll
                for (int i = 1; i < 16; i++) mx = fmaxf(mx, red[i]);
                const float sA = fmaxf(mx, 1e-30f);
                if (tid == 0) sA_sm[cs.v] = sA;   // later folds ordered via mbar chain
                const float inv = 16256.0f / sA;
                const size_t vb = (size_t)cs.v * (BATCH * WIDTH);
#pragma unroll
                for (int mi = 0; mi < 2; mi++)
#pragma unroll
                    for (int ni = 0; ni < 4; ni++) {
                        const float4 sv = sumv[(mi * 4 + ni) * 512 + tid];
                        const int col = warp_noff + 2 * (lane & 3) + ni * 8;
                        const int r0  = row0 + warp_moff + mi * 16 + (lane >> 2);
                        int h0, l0, h1, l1, h2, l2, h3, l3;
                        quant2(sv.x, inv, h0, l0); quant2(sv.y, inv, h1, l1);
                        quant2(sv.z, inv, h2, l2); quant2(sv.w, inv, h3, l3);
                        *(char2*)(g_A1 + vb + (size_t)r0 * WIDTH + col)       = make_char2((char)h0, (char)h1);
                        *(char2*)(g_A0 + vb + (size_t)r0 * WIDTH + col)       = make_char2((char)l0, (char)l1);
                        *(char2*)(g_A1 + vb + (size_t)(r0 + 8) * WIDTH + col) = make_char2((char)h2, (char)h3);
                        *(char2*)(g_A0 + vb + (size_t)(r0 + 8) * WIDTH + col) = make_char2((char)l2, (char)l3);
                    }
                __threadfence();
            }
        }

        if (lane == 0) mbar_arrive(sbase + MB_EMPTY(s));
        cs.advance();
    }
}

// ---------------- launch ----------------
extern "C" void kernel_launch(void* const* d_in, const int* in_sizes, int n_in,
                              void* d_out, int out_size) {
    const float* x = (const float*)d_in[0];
    const float* W = (const float*)d_in[1];
    const float* b = (const float*)d_in[2];
    float* out = (float*)d_out;

    cudaFuncSetAttribute(node_fused_kernel,
                         cudaFuncAttributeMaxDynamicSharedMemorySize, SMEM_TOTAL);

    w_prep_kernel<<<NEDGES, dim3(32, 8)>>>(W);
    node_fused_kernel<<<BATCH / BM, THREADS, SMEM_TOTAL>>>(x, b, out);
}